// round 2
// baseline (speedup 1.0000x reference)
#include <cuda_runtime.h>
#include <math.h>

// Problem dims
#define BB 64
#define TT 32
#define CC 2048
#define DD 1024

// Scratch (allocation-free rule: __device__ globals). Layout [t][b][d].
__device__ float g_H [TT * BB * DD];   // gelu(enc1 out)
__device__ float g_H2[TT * BB * DD];   // enc2 out (pre-LN)
__device__ float g_Z [TT * BB * DD];   // latent after LN+noise+clip
__device__ float g_G [TT * BB * DD];   // gelu(dec1 out)

__device__ __forceinline__ float gelu_f(float x) {
    // exact GELU: x * 0.5 * (1 + erf(x / sqrt(2)))
    return 0.5f * x * (1.0f + erff(x * 0.70710678118654752440f));
}

// Generic batched GEMM: C[t] (64 x N) = A[t] (64 x K) * B[t] (K x N)
// A rows are batch b (M = 64 always). B is [T][K][N] row-major (weights).
// FUSE_NOISE: A := A2*1e-4 + A*(1-1e-4) on load (input noise mix).
// GELU_EPI:   apply exact gelu before storing C.
// Tiling: BM=64, BN=64, BK=16, 256 threads, 4x4 per-thread tile.
template<bool FUSE_NOISE, bool GELU_EPI>
__global__ __launch_bounds__(256, 4) void gemm64_kernel(
    const float* __restrict__ A, const float* __restrict__ A2,
    long a_tstride, int lda,
    const float* __restrict__ Bw,          // [T][K][N]
    float* __restrict__ Co, long c_tstride, int ldc,
    int K, int N)
{
    const int t   = blockIdx.y;
    const int nb  = blockIdx.x * 64;
    const int tid = threadIdx.x;

    __shared__ float As[16][68];   // [k][m], padded stride 68 (16B aligned, low conflict)
    __shared__ float Bs[16][64];   // [k][n]

    const int tx = tid & 15;       // n-direction (cols tx*4 .. tx*4+3)
    const int ty = tid >> 4;       // m-direction (rows ty*4 .. ty*4+3)

    // A tile load mapping: row ar (0..63), k-quad akq (0,4,8,12)
    const int ar  = tid >> 2;
    const int akq = (tid & 3) * 4;
    // B tile load mapping: row br (0..15), col quad bc
    const int br  = tid >> 4;
    const int bc  = (tid & 15) * 4;

    const float* Abase  = A + (long)t * a_tstride + (long)ar * lda;
    const float* A2base = FUSE_NOISE ? (A2 + (long)t * a_tstride + (long)ar * lda) : nullptr;
    const float* Bbase  = Bw + (long)t * K * N + (long)br * N + nb + bc;

    float acc[4][4] = {};

    for (int kt = 0; kt < K; kt += 16) {
        float4 a4 = *reinterpret_cast<const float4*>(Abase + kt + akq);
        if (FUSE_NOISE) {
            float4 n4 = *reinterpret_cast<const float4*>(A2base + kt + akq);
            const float f = 1e-4f, g = 1.0f - 1e-4f;
            a4.x = n4.x * f + a4.x * g;
            a4.y = n4.y * f + a4.y * g;
            a4.z = n4.z * f + a4.z * g;
            a4.w = n4.w * f + a4.w * g;
        }
        float4 b4 = *reinterpret_cast<const float4*>(Bbase + (long)kt * N);

        __syncthreads();  // previous tile fully consumed before overwrite
        As[akq + 0][ar] = a4.x;
        As[akq + 1][ar] = a4.y;
        As[akq + 2][ar] = a4.z;
        As[akq + 3][ar] = a4.w;
        *reinterpret_cast<float4*>(&Bs[br][bc]) = b4;
        __syncthreads();

        #pragma unroll
        for (int k = 0; k < 16; k++) {
            float4 avv = *reinterpret_cast<const float4*>(&As[k][ty * 4]);
            float4 bvv = *reinterpret_cast<const float4*>(&Bs[k][tx * 4]);
            float av[4] = {avv.x, avv.y, avv.z, avv.w};
            float bv[4] = {bvv.x, bvv.y, bvv.z, bvv.w};
            #pragma unroll
            for (int i = 0; i < 4; i++)
                #pragma unroll
                for (int j = 0; j < 4; j++)
                    acc[i][j] += av[i] * bv[j];
        }
    }

    float* Cbase = Co + (long)t * c_tstride + nb;
    #pragma unroll
    for (int i = 0; i < 4; i++) {
        #pragma unroll
        for (int j = 0; j < 4; j++) {
            float v = acc[i][j];
            if (GELU_EPI) v = gelu_f(v);
            Cbase[(long)(ty * 4 + i) * ldc + tx * 4 + j] = v;
        }
    }
}

// Fused LayerNorm + latent noise + clamp.
// One block per row r = t*BB + b of H2 (layout [t][b][d], D = 1024).
// noise_z layout is [b][t][d].
__global__ __launch_bounds__(256) void ln_kernel(
    const float* __restrict__ H2, const float* __restrict__ noise_z,
    const float* __restrict__ gamma, const float* __restrict__ beta,
    float* __restrict__ Z)
{
    const int r = blockIdx.x;
    const int t = r >> 6;    // / BB
    const int b = r & 63;    // % BB
    const int tid = threadIdx.x;

    const float* h  = H2 + (long)r * DD;
    const float* nz = noise_z + ((long)b * TT + t) * DD;
    float*       z  = Z + (long)r * DD;

    float4 hv = *reinterpret_cast<const float4*>(h + tid * 4);
    float s  = hv.x + hv.y + hv.z + hv.w;
    float ss = hv.x * hv.x + hv.y * hv.y + hv.z * hv.z + hv.w * hv.w;

    #pragma unroll
    for (int off = 16; off > 0; off >>= 1) {
        s  += __shfl_xor_sync(0xffffffffu, s,  off);
        ss += __shfl_xor_sync(0xffffffffu, ss, off);
    }

    __shared__ float ws[8], wss[8];
    const int lane = tid & 31, wid = tid >> 5;
    if (lane == 0) { ws[wid] = s; wss[wid] = ss; }
    __syncthreads();

    float mu = 0.f, m2 = 0.f;
    #pragma unroll
    for (int i = 0; i < 8; i++) { mu += ws[i]; m2 += wss[i]; }
    mu *= (1.0f / DD);
    float var  = m2 * (1.0f / DD) - mu * mu;
    float rstd = rsqrtf(var + 1e-5f);

    float4 nv = *reinterpret_cast<const float4*>(nz + tid * 4);
    float4 g4 = *reinterpret_cast<const float4*>(gamma + tid * 4);
    float4 b4 = *reinterpret_cast<const float4*>(beta + tid * 4);

    const float fl = 1e-3f, gl = 1.0f - 1e-3f;
    float4 ov;
    float v;
    v = (hv.x - mu) * rstd * g4.x + b4.x; v = nv.x * fl + v * gl; ov.x = fminf(1.0f, fmaxf(-1.0f, v));
    v = (hv.y - mu) * rstd * g4.y + b4.y; v = nv.y * fl + v * gl; ov.y = fminf(1.0f, fmaxf(-1.0f, v));
    v = (hv.z - mu) * rstd * g4.z + b4.z; v = nv.z * fl + v * gl; ov.z = fminf(1.0f, fmaxf(-1.0f, v));
    v = (hv.w - mu) * rstd * g4.w + b4.w; v = nv.w * fl + v * gl; ov.w = fminf(1.0f, fmaxf(-1.0f, v));
    *reinterpret_cast<float4*>(z + tid * 4) = ov;
}

extern "C" void kernel_launch(void* const* d_in, const int* in_sizes, int n_in,
                              void* d_out, int out_size) {
    const float* x       = (const float*)d_in[0];
    const float* noise_x = (const float*)d_in[1];
    const float* noise_z = (const float*)d_in[2];
    const float* enc_w1  = (const float*)d_in[3];   // [T][C][D]
    const float* enc_w2  = (const float*)d_in[4];   // [T][D][D]
    const float* dec_w1  = (const float*)d_in[5];   // [T][D][D]
    const float* dec_w2  = (const float*)d_in[6];   // [T][D][C]
    const float* ln_g    = (const float*)d_in[7];
    const float* ln_b    = (const float*)d_in[8];
    float* out = (float*)d_out;

    float *H, *H2, *Z, *G;
    cudaGetSymbolAddress((void**)&H,  g_H);
    cudaGetSymbolAddress((void**)&H2, g_H2);
    cudaGetSymbolAddress((void**)&Z,  g_Z);
    cudaGetSymbolAddress((void**)&G,  g_G);

    // 1) enc1: H[t][b][d] = gelu( (noise-mixed x chunk) @ enc_w1[t] )
    gemm64_kernel<true, true><<<dim3(DD / 64, TT), 256>>>(
        x, noise_x, (long)CC, TT * CC, enc_w1, H, (long)BB * DD, DD, CC, DD);

    // 2) enc2: H2 = H @ enc_w2[t]
    gemm64_kernel<false, false><<<dim3(DD / 64, TT), 256>>>(
        H, nullptr, (long)BB * DD, DD, enc_w2, H2, (long)BB * DD, DD, DD, DD);

    // 3) LayerNorm + latent noise + clamp -> Z
    ln_kernel<<<TT * BB, 256>>>(H2, noise_z, ln_g, ln_b, Z);

    // 4) dec1: G = gelu( Z @ dec_w1[t] )
    gemm64_kernel<false, true><<<dim3(DD / 64, TT), 256>>>(
        Z, nullptr, (long)BB * DD, DD, dec_w1, G, (long)BB * DD, DD, DD, DD);

    // 5) dec2: out[b][t*C + c] = G @ dec_w2[t]
    gemm64_kernel<false, false><<<dim3(CC / 64, TT), 256>>>(
        G, nullptr, (long)BB * DD, DD, dec_w2, out, (long)CC, TT * CC, DD, CC);
}

// round 7
// speedup vs baseline: 1.1150x; 1.1150x over previous
#include <cuda_runtime.h>
#include <math.h>

#define BB 64
#define TT 32
#define CC 2048
#define DD 1024

// Scratch (__device__ globals; allocation-free rule)
__device__ float g_XN[BB * TT * CC];   // noise-mixed input (16 MB)
__device__ float g_H [TT * BB * DD];   // gelu(enc1 out)
__device__ float g_H2[TT * BB * DD];   // enc2 out (pre-LN)
__device__ float g_Z [TT * BB * DD];   // latent
__device__ float g_G [TT * BB * DD];   // gelu(dec1 out)

__device__ __forceinline__ float gelu_f(float x) {
    return 0.5f * x * (1.0f + erff(x * 0.70710678118654752440f));
}

// Packed fp32x2 FMA (Blackwell): acc = a*b + acc elementwise on both 32-bit halves.
#define FFMA2(acc, a, b) asm("fma.rn.f32x2 %0, %1, %2, %0;" : "+l"(acc) : "l"(a), "l"(b))
// Duplicate one float into both halves of a 64-bit packed register.
#define PACK2(d, x)      asm("mov.b64 %0, {%1, %1};" : "=l"(d) : "r"(__float_as_uint(x)))
// 128-bit shared load straight into two packed-u64 registers (16B aligned).
#define LDSV2U64(d0, d1, a) asm("ld.shared.v2.u64 {%0, %1}, [%2];" : "=l"(d0), "=l"(d1) : "r"(a))
#define UNPACK2(lo, hi, v)  asm("mov.b64 {%0, %1}, %2;" : "=f"(lo), "=f"(hi) : "l"(v))

// ---------------------------------------------------------------------------
// Noise-mix pre-pass: xn = noise_x * 1e-4 + x * (1 - 1e-4)  (elementwise)
// ---------------------------------------------------------------------------
__global__ __launch_bounds__(256) void mix_kernel(
    const float* __restrict__ x, const float* __restrict__ nx,
    float* __restrict__ xn, int n4)
{
    int i = blockIdx.x * 256 + threadIdx.x;
    if (i >= n4) return;
    float4 a = reinterpret_cast<const float4*>(x)[i];
    float4 b = reinterpret_cast<const float4*>(nx)[i];
    const float f = 1e-4f, g = 1.0f - 1e-4f;
    float4 o;
    o.x = b.x * f + a.x * g;
    o.y = b.y * f + a.y * g;
    o.z = b.z * f + a.z * g;
    o.w = b.w * f + a.w * g;
    reinterpret_cast<float4*>(xn)[i] = o;
}

// ---------------------------------------------------------------------------
// Batched GEMM: C[t] (64 x N) = A[t] (64 x K) @ Bw[t] (K x N)
// BM=64 (full M), BN=256, BK=16. 128 threads. Per-thread tile 8(m) x 16(n),
// computed with packed f32x2 FMAs (64 FFMA2 per k per thread).
// Thread (ty=tid>>4 in 0..7, tx=tid&15): rows {ty*4..+3} U {ty*4+32..+3},
// cols {tx*4 + j*64 .. +3} for j=0..3.
// ---------------------------------------------------------------------------
template<bool GELU_EPI>
__global__ __launch_bounds__(128) void gemm64x256(
    const float* __restrict__ A, long a_tstride, int lda,
    const float* __restrict__ Bw,           // [T][K][N]
    float* __restrict__ Co, long c_tstride, int ldc,
    int K, int N)
{
    const int t   = blockIdx.y;
    const int nb  = blockIdx.x * 256;
    const int tid = threadIdx.x;
    const int tx  = tid & 15;
    const int ty  = tid >> 4;

    __shared__ __align__(16) float As[16][68];    // [k][m], padded
    __shared__ __align__(16) float Bs[16][256];   // [k][n]

    // Global load mapping
    const int ar  = tid >> 1;            // A row 0..63
    const int akq = (tid & 1) * 8;       // A k-offset 0 or 8 (2x float4)
    const int br  = tid >> 4;            // B row 0..7 (also br+8)
    const int bc  = (tid & 15) * 4;      // B col quad base

    const float* Ab = A + (long)t * a_tstride + (long)ar * lda + akq;
    const float* Bb = Bw + (long)t * K * N + nb + bc;

    unsigned long long acc[2][4][8];
    #pragma unroll
    for (int ms = 0; ms < 2; ms++)
        #pragma unroll
        for (int r = 0; r < 4; r++)
            #pragma unroll
            for (int j = 0; j < 8; j++) acc[ms][r][j] = 0ull;

    // Prefetch first tile into registers
    float4 pa0, pa1, pb[8];
    pa0 = *reinterpret_cast<const float4*>(Ab);
    pa1 = *reinterpret_cast<const float4*>(Ab + 4);
    #pragma unroll
    for (int rj = 0; rj < 8; rj++) {
        int rr = (rj >> 2) * 8;         // 0 or 8
        int jj = (rj & 3) * 64;
        pb[rj] = *reinterpret_cast<const float4*>(Bb + (long)(br + rr) * N + jj);
    }

    unsigned sB = (unsigned)__cvta_generic_to_shared(&Bs[0][0]);

    for (int kt = 0; kt < K; kt += 16) {
        // Fill smem from prefetch regs
        #pragma unroll
        for (int j = 0; j < 4; j++) {
            As[akq + j][ar]     = (&pa0.x)[j];
            As[akq + 4 + j][ar] = (&pa1.x)[j];
        }
        #pragma unroll
        for (int rj = 0; rj < 8; rj++) {
            int rr = (rj >> 2) * 8;
            int jj = (rj & 3) * 64;
            *reinterpret_cast<float4*>(&Bs[br + rr][bc + jj]) = pb[rj];
        }
        __syncthreads();

        // Prefetch next tile (overlaps with compute below)
        if (kt + 16 < K) {
            pa0 = *reinterpret_cast<const float4*>(Ab + kt + 16);
            pa1 = *reinterpret_cast<const float4*>(Ab + kt + 20);
            #pragma unroll
            for (int rj = 0; rj < 8; rj++) {
                int rr = (rj >> 2) * 8;
                int jj = (rj & 3) * 64;
                pb[rj] = *reinterpret_cast<const float4*>(
                    Bb + (long)(kt + 16 + br + rr) * N + jj);
            }
        }

        // Compute 16 k-steps
        #pragma unroll
        for (int k = 0; k < 16; k++) {
            unsigned long long b64[8];
            #pragma unroll
            for (int j = 0; j < 4; j++) {
                unsigned addr = sB + (unsigned)((k * 256 + tx * 4 + j * 64) << 2);
                LDSV2U64(b64[2 * j], b64[2 * j + 1], addr);
            }
            float4 av0 = *reinterpret_cast<const float4*>(&As[k][ty * 4]);
            float4 av1 = *reinterpret_cast<const float4*>(&As[k][ty * 4 + 32]);
            unsigned long long a64[8];
            PACK2(a64[0], av0.x); PACK2(a64[1], av0.y);
            PACK2(a64[2], av0.z); PACK2(a64[3], av0.w);
            PACK2(a64[4], av1.x); PACK2(a64[5], av1.y);
            PACK2(a64[6], av1.z); PACK2(a64[7], av1.w);
            #pragma unroll
            for (int ms = 0; ms < 2; ms++)
                #pragma unroll
                for (int r = 0; r < 4; r++)
                    #pragma unroll
                    for (int j = 0; j < 8; j++)
                        FFMA2(acc[ms][r][j], a64[ms * 4 + r], b64[j]);
        }
        __syncthreads();
    }

    // Epilogue
    float* Cb = Co + (long)t * c_tstride + nb;
    #pragma unroll
    for (int ms = 0; ms < 2; ms++) {
        #pragma unroll
        for (int r = 0; r < 4; r++) {
            int m = ty * 4 + r + ms * 32;
            float* row = Cb + (long)m * ldc + tx * 4;
            #pragma unroll
            for (int j = 0; j < 4; j++) {
                float v0, v1, v2, v3;
                UNPACK2(v0, v1, acc[ms][r][2 * j]);
                UNPACK2(v2, v3, acc[ms][r][2 * j + 1]);
                float4 v;
                if (GELU_EPI) {
                    v.x = gelu_f(v0); v.y = gelu_f(v1);
                    v.z = gelu_f(v2); v.w = gelu_f(v3);
                } else {
                    v.x = v0; v.y = v1; v.z = v2; v.w = v3;
                }
                *reinterpret_cast<float4*>(row + j * 64) = v;
            }
        }
    }
}

// ---------------------------------------------------------------------------
// Fused LayerNorm + latent noise + clamp. One block per row r=t*BB+b, D=1024.
// noise_z layout is [b][t][d].
// ---------------------------------------------------------------------------
__global__ __launch_bounds__(256) void ln_kernel(
    const float* __restrict__ H2, const float* __restrict__ noise_z,
    const float* __restrict__ gamma, const float* __restrict__ beta,
    float* __restrict__ Z)
{
    const int r = blockIdx.x;
    const int t = r >> 6;
    const int b = r & 63;
    const int tid = threadIdx.x;

    const float* h  = H2 + (long)r * DD;
    const float* nz = noise_z + ((long)b * TT + t) * DD;
    float*       z  = Z + (long)r * DD;

    float4 hv = *reinterpret_cast<const float4*>(h + tid * 4);
    float s  = hv.x + hv.y + hv.z + hv.w;
    float ss = hv.x * hv.x + hv.y * hv.y + hv.z * hv.z + hv.w * hv.w;

    #pragma unroll
    for (int off = 16; off > 0; off >>= 1) {
        s  += __shfl_xor_sync(0xffffffffu, s,  off);
        ss += __shfl_xor_sync(0xffffffffu, ss, off);
    }
    __shared__ float ws[8], wss[8];
    const int lane = tid & 31, wid = tid >> 5;
    if (lane == 0) { ws[wid] = s; wss[wid] = ss; }
    __syncthreads();

    float mu = 0.f, m2 = 0.f;
    #pragma unroll
    for (int i = 0; i < 8; i++) { mu += ws[i]; m2 += wss[i]; }
    mu *= (1.0f / DD);
    float var  = m2 * (1.0f / DD) - mu * mu;
    float rstd = rsqrtf(var + 1e-5f);

    float4 nv = *reinterpret_cast<const float4*>(nz + tid * 4);
    float4 g4 = *reinterpret_cast<const float4*>(gamma + tid * 4);
    float4 b4 = *reinterpret_cast<const float4*>(beta + tid * 4);

    const float fl = 1e-3f, gl = 1.0f - 1e-3f;
    float4 ov; float v;
    v = (hv.x - mu) * rstd * g4.x + b4.x; v = nv.x * fl + v * gl; ov.x = fminf(1.0f, fmaxf(-1.0f, v));
    v = (hv.y - mu) * rstd * g4.y + b4.y; v = nv.y * fl + v * gl; ov.y = fminf(1.0f, fmaxf(-1.0f, v));
    v = (hv.z - mu) * rstd * g4.z + b4.z; v = nv.z * fl + v * gl; ov.z = fminf(1.0f, fmaxf(-1.0f, v));
    v = (hv.w - mu) * rstd * g4.w + b4.w; v = nv.w * fl + v * gl; ov.w = fminf(1.0f, fmaxf(-1.0f, v));
    *reinterpret_cast<float4*>(z + tid * 4) = ov;
}

extern "C" void kernel_launch(void* const* d_in, const int* in_sizes, int n_in,
                              void* d_out, int out_size) {
    const float* x       = (const float*)d_in[0];
    const float* noise_x = (const float*)d_in[1];
    const float* noise_z = (const float*)d_in[2];
    const float* enc_w1  = (const float*)d_in[3];   // [T][C][D]
    const float* enc_w2  = (const float*)d_in[4];   // [T][D][D]
    const float* dec_w1  = (const float*)d_in[5];   // [T][D][D]
    const float* dec_w2  = (const float*)d_in[6];   // [T][D][C]
    const float* ln_g    = (const float*)d_in[7];
    const float* ln_b    = (const float*)d_in[8];
    float* out = (float*)d_out;

    float *XN, *H, *H2, *Z, *G;
    cudaGetSymbolAddress((void**)&XN, g_XN);
    cudaGetSymbolAddress((void**)&H,  g_H);
    cudaGetSymbolAddress((void**)&H2, g_H2);
    cudaGetSymbolAddress((void**)&Z,  g_Z);
    cudaGetSymbolAddress((void**)&G,  g_G);

    // 0) noise-mix x into dedicated 16MB scratch
    {
        int n4 = BB * TT * CC / 4;  // 1,048,576 float4
        mix_kernel<<<n4 / 256, 256>>>(x, noise_x, XN, n4);
    }

    // 1) enc1: H[t][b][d] = gelu( xn_chunk @ enc_w1[t] )   (xn rows stride T*C)
    gemm64x256<true><<<dim3(DD / 256, TT), 128>>>(
        XN, (long)CC, TT * CC, enc_w1, H, (long)BB * DD, DD, CC, DD);

    // 2) enc2: H2 = H @ enc_w2[t]
    gemm64x256<false><<<dim3(DD / 256, TT), 128>>>(
        H, (long)BB * DD, DD, enc_w2, H2, (long)BB * DD, DD, DD, DD);

    // 3) LayerNorm + latent noise + clamp -> Z
    ln_kernel<<<TT * BB, 256>>>(H2, noise_z, ln_g, ln_b, Z);

    // 4) dec1: G = gelu( Z @ dec_w1[t] )
    gemm64x256<true><<<dim3(DD / 256, TT), 128>>>(
        Z, (long)BB * DD, DD, dec_w1, G, (long)BB * DD, DD, DD, DD);

    // 5) dec2: out[b][t*C + c] = G @ dec_w2[t]
    gemm64x256<false><<<dim3(CC / 256, TT), 128>>>(
        G, (long)BB * DD, DD, dec_w2, out, (long)CC, TT * CC, DD, CC);
}